// round 2
// baseline (speedup 1.0000x reference)
#include <cuda_runtime.h>

#define N_NODES 100000
#define N_EDGES 1600000
#define IN_DIM  256
#define HID     128
#define OUT_DIM 40

typedef unsigned long long u64;

// ---- scratch (static device globals; allocation-free per harness rules) ----
__device__ float g_deg[N_NODES];
__device__ float g_isd[N_NODES];
__device__ float g_h1[(size_t)N_NODES * HID];    // h1' = (x@W1)*isd[row]
__device__ float g_agg1[(size_t)N_NODES * HID];  // sum of h1'[src]
__device__ float g_h2[(size_t)N_NODES * OUT_DIM];// h2' = (relu(...)@W2)*isd[row]

#define FMA2(d, a, b) asm("fma.rn.f32x2 %0, %1, %2, %3;" : "=l"(d) : "l"(a), "l"(b), "l"(d))

// ---------------------------------------------------------------- degree ----
__global__ void k_zero_deg(int n) {
    int i = blockIdx.x * blockDim.x + threadIdx.x;
    if (i < n) g_deg[i] = 0.f;
}

__global__ void k_count(const int* __restrict__ dst, int e) {
    int i = blockIdx.x * blockDim.x + threadIdx.x;
    if (i < e) atomicAdd(&g_deg[dst[i]], 1.0f);
}

__global__ void k_isd(int n) {
    int i = blockIdx.x * blockDim.x + threadIdx.x;
    if (i < n) {
        float d = g_deg[i];
        g_isd[i] = (d > 0.f) ? rsqrtf(d) : 0.f;
    }
}

// ---------------------------------------------------------------- GEMM1 -----
// h1'[N,128] = (x[N,256] @ W1[256,128]) * isd[row].
// BM=64, BN=128 (full), BK=32, 256 threads. Packed fp32x2 FFMA2 mainloop.
// A tile stored TRANSPOSED + DUPLICATED: sA2[k][2m]=sA2[k][2m+1]=A[m][k],
// so the (a,a) operand is a single LDS.128 broadcast (no mov.b64 packing).
__global__ void __launch_bounds__(256, 2)
k_gemm1(const float* __restrict__ x, const float* __restrict__ W, int n) {
    __shared__ float sA2[32][132];  // [k][2*m], stride 132 (16B-aligned rows)
    __shared__ float sB[32][128];   // [k][n]
    int tid = threadIdx.x;
    int tx = tid & 31, ty = tid >> 5;
    int m0 = blockIdx.x * 64;

    u64 acc01[8], acc23[8];
    #pragma unroll
    for (int mm = 0; mm < 8; mm++) { acc01[mm] = 0ULL; acc23[mm] = 0ULL; }

    for (int k0 = 0; k0 < IN_DIM; k0 += 32) {
        // A tile: 64 rows x 32 k. Each thread loads 2 float4, scatters dup-transposed.
        #pragma unroll
        for (int j = 0; j < 2; j++) {
            int i = tid + j * 256;
            int r = i >> 3, c = (i & 7) * 4;       // r = m-row, c = k-offset
            int row = m0 + r;
            float4 v = (row < n) ? *(const float4*)&x[(size_t)row * IN_DIM + k0 + c]
                                 : make_float4(0.f, 0.f, 0.f, 0.f);
            *(float2*)&sA2[c + 0][2 * r] = make_float2(v.x, v.x);
            *(float2*)&sA2[c + 1][2 * r] = make_float2(v.y, v.y);
            *(float2*)&sA2[c + 2][2 * r] = make_float2(v.z, v.z);
            *(float2*)&sA2[c + 3][2 * r] = make_float2(v.w, v.w);
        }
        // B tile: 32x128
        #pragma unroll
        for (int j = 0; j < 4; j++) {
            int i = tid + j * 256;
            int r = i >> 5, c = (i & 31) * 4;
            *(float4*)&sB[r][c] = *(const float4*)&W[(size_t)(k0 + r) * HID + c];
        }
        __syncthreads();

        #pragma unroll
        for (int k = 0; k < 32; k++) {
            double2 b = *(double2*)&sB[k][tx * 4];
            u64 b01 = __double_as_longlong(b.x);
            u64 b23 = __double_as_longlong(b.y);
            u64 am[8];
            #pragma unroll
            for (int q = 0; q < 4; q++) {
                double2 a = *(double2*)&sA2[k][ty * 16 + q * 4];  // broadcast
                am[2 * q + 0] = __double_as_longlong(a.x);
                am[2 * q + 1] = __double_as_longlong(a.y);
            }
            #pragma unroll
            for (int mm = 0; mm < 8; mm++) {
                FMA2(acc01[mm], am[mm], b01);
                FMA2(acc23[mm], am[mm], b23);
            }
        }
        __syncthreads();
    }
    #pragma unroll
    for (int mm = 0; mm < 8; mm++) {
        int row = m0 + ty * 8 + mm;
        if (row < n) {
            float s = g_isd[row];
            float2 f01 = *(float2*)&acc01[mm];
            float2 f23 = *(float2*)&acc23[mm];
            float4 v = make_float4(f01.x * s, f01.y * s, f23.x * s, f23.y * s);
            *(float4*)&g_h1[(size_t)row * HID + tx * 4] = v;
        }
    }
}

// ------------------------------------------------------- layer1 edge agg ----
__global__ void k_zero_agg1(int n) {
    int i = blockIdx.x * blockDim.x + threadIdx.x;  // over n*32 float4
    if (i < n * 32) ((float4*)g_agg1)[i] = make_float4(0.f, 0.f, 0.f, 0.f);
}

// warp per edge: pure accumulation (scaling folded into producers/consumers).
__global__ void k_edge1(const int* __restrict__ src, const int* __restrict__ dst, int e) {
    int gid = blockIdx.x * blockDim.x + threadIdx.x;
    int w = gid >> 5;
    int lane = threadIdx.x & 31;
    if (w >= e) return;
    int s = __ldg(&src[w]);
    int d = __ldg(&dst[w]);
    float4 v = ((const float4*)g_h1)[(size_t)s * 32 + lane];
    float* p = (float*)(((float4*)g_agg1) + ((size_t)d * 32 + lane));
    asm volatile("red.global.add.v4.f32 [%0], {%1,%2,%3,%4};"
                 :: "l"(p), "f"(v.x), "f"(v.y), "f"(v.z), "f"(v.w) : "memory");
}

// ---------------------------------------------------------------- GEMM2 -----
// h2'[N,40] = (relu(isd[row]*agg1 + b1)[N,128] @ W2[128,40]) * isd[row].
__global__ void k_gemm2(const float* __restrict__ W2, const float* __restrict__ b1, int n) {
    __shared__ float sW[HID * OUT_DIM];  // 20 KB
    __shared__ float sA[32][129];        // pad -> conflict-free
    int tid = threadIdx.x;
    int m0 = blockIdx.x * 32;

    for (int i = tid; i < HID * OUT_DIM; i += 256) sW[i] = W2[i];

    // A tile: 32x128, fused isd-scale + bias + relu
    #pragma unroll
    for (int j = 0; j < 4; j++) {
        int i = tid + j * 256;
        int r = i >> 5, c = (i & 31) * 4;
        int row = m0 + r;
        float4 v = make_float4(0.f, 0.f, 0.f, 0.f);
        float s = 0.f;
        if (row < n) {
            v = *(const float4*)&g_agg1[(size_t)row * HID + c];
            s = g_isd[row];
        }
        float4 bb = *(const float4*)&b1[c];
        sA[r][c + 0] = fmaxf(fmaf(s, v.x, bb.x), 0.f);
        sA[r][c + 1] = fmaxf(fmaf(s, v.y, bb.y), 0.f);
        sA[r][c + 2] = fmaxf(fmaf(s, v.z, bb.z), 0.f);
        sA[r][c + 3] = fmaxf(fmaf(s, v.w, bb.w), 0.f);
    }
    __syncthreads();

    int m = tid & 31, g = tid >> 5;
    float acc[5] = {};
    #pragma unroll 8
    for (int k = 0; k < HID; k++) {
        float a = sA[m][k];
        #pragma unroll
        for (int j = 0; j < 5; j++)
            acc[j] = fmaf(a, sW[k * OUT_DIM + g * 5 + j], acc[j]);
    }
    int row = m0 + m;
    if (row < n) {
        float s = g_isd[row];
        #pragma unroll
        for (int j = 0; j < 5; j++)
            g_h2[(size_t)row * OUT_DIM + g * 5 + j] = acc[j] * s;
    }
}

// ------------------------------------------------------- layer2 edge agg ----
__global__ void k_zero_out(float* __restrict__ out, int n) {
    int i = blockIdx.x * blockDim.x + threadIdx.x;  // over n*10 float4
    if (i < n * 10) ((float4*)out)[i] = make_float4(0.f, 0.f, 0.f, 0.f);
}

// thread per (edge, float4-chunk): pure accumulation.
__global__ void k_edge2(const int* __restrict__ src, const int* __restrict__ dst,
                        float* __restrict__ out, int e) {
    int i = blockIdx.x * blockDim.x + threadIdx.x;
    if (i >= e * 10) return;
    int w = i / 10;
    int c = i - w * 10;
    int s = __ldg(&src[w]);
    int d = __ldg(&dst[w]);
    float4 v = ((const float4*)g_h2)[(size_t)s * 10 + c];
    float* p = (float*)(((float4*)out) + ((size_t)d * 10 + c));
    asm volatile("red.global.add.v4.f32 [%0], {%1,%2,%3,%4};"
                 :: "l"(p), "f"(v.x), "f"(v.y), "f"(v.z), "f"(v.w) : "memory");
}

// out = isd[row] * acc + b2
__global__ void k_final(float* __restrict__ out, const float* __restrict__ b2, int n) {
    int i = blockIdx.x * blockDim.x + threadIdx.x;  // over n*10 float4
    if (i >= n * 10) return;
    int c = i - (i / 10) * 10;
    int row = i / 10;
    float s = g_isd[row];
    float4 v = ((float4*)out)[i];
    float4 bb = ((const float4*)b2)[c];
    v.x = fmaf(s, v.x, bb.x);
    v.y = fmaf(s, v.y, bb.y);
    v.z = fmaf(s, v.z, bb.z);
    v.w = fmaf(s, v.w, bb.w);
    ((float4*)out)[i] = v;
}

// ---------------------------------------------------------------- launch ----
extern "C" void kernel_launch(void* const* d_in, const int* in_sizes, int n_in,
                              void* d_out, int out_size) {
    const float* x   = (const float*)d_in[0];
    const int*   src = (const int*)d_in[1];
    const int*   dst = (const int*)d_in[2];
    const float* W1  = (const float*)d_in[3];
    const float* b1  = (const float*)d_in[4];
    const float* W2  = (const float*)d_in[5];
    const float* b2  = (const float*)d_in[6];
    float* out = (float*)d_out;

    int n = in_sizes[0] / IN_DIM;
    int e = in_sizes[1];

    k_zero_deg<<<(n + 255) / 256, 256>>>(n);
    k_count<<<(e + 255) / 256, 256>>>(dst, e);
    k_isd<<<(n + 255) / 256, 256>>>(n);

    k_gemm1<<<(n + 63) / 64, 256>>>(x, W1, n);
    k_zero_agg1<<<(n * 32 + 255) / 256, 256>>>(n);
    k_edge1<<<((e * 32) + 255) / 256, 256>>>(src, dst, e);

    k_gemm2<<<(n + 31) / 32, 256>>>(W2, b1, n);
    k_zero_out<<<(n * 10 + 255) / 256, 256>>>(out, n);
    k_edge2<<<((e * 10) + 255) / 256, 256>>>(src, dst, out, e);
    k_final<<<(n * 10 + 255) / 256, 256>>>(out, b2, n);
}